// round 9
// baseline (speedup 1.0000x reference)
#include <cuda_runtime.h>
#include <math.h>

#define SEQ   256
#define BATCH 32
#define DIM   512
#define MDIM  256            // N_TAPES*HEAD_DIM
#define G4    2048           // 4*DIM
#define AQ    296            // 40 action + 256 query
#define ROWS  8192           // SEQ*BATCH

// ---------------- device scratch (static globals; no allocation) ----------------
__device__ float g_gates [(size_t)ROWS * G4];              // x@Wih + bih + bhh
__device__ float g_hidden[(size_t)(SEQ + 1) * BATCH * DIM];// slot t = h_{t-1}
__device__ float g_values[(size_t)ROWS * MDIM];
__device__ float g_keys  [(size_t)ROWS * MDIM];
__device__ float g_actq  [(size_t)ROWS * AQ];              // hidden part of act|query (+bias)
__device__ float g_ro    [(size_t)ROWS * MDIM];            // gated read_out per step
__device__ float g_Wt    [(size_t)DIM * DIM * 4];          // Whh transposed [d][k][gate]
__device__ float g_Wcat  [(size_t)(DIM + MDIM) * AQ];      // [Wa | Wq] fused, rows = D+M
__device__ float g_bcat  [AQ];
__device__ float g_bsum  [G4];
__device__ unsigned g_barcnt;

__device__ __forceinline__ float sigf(float x) { return 1.f / (1.f + expf(-x)); }

// ---------------- init: transpose Whh, fuse Wa|Wq, biases, zero state ----------------
__global__ void init_kernel(const float* __restrict__ Whh,
                            const float* __restrict__ bih, const float* __restrict__ bhh,
                            const float* __restrict__ Wa,  const float* __restrict__ ba,
                            const float* __restrict__ Wq,  const float* __restrict__ bq) {
    int idx = blockIdx.x * blockDim.x + threadIdx.x;   // up to 1,048,576
    if (idx < DIM * DIM * 4) {
        int g = idx & 3;
        int k = (idx >> 2) & (DIM - 1);
        int d = idx >> 11;
        g_Wt[idx] = Whh[(size_t)k * G4 + g * DIM + d];
    }
    if (idx < (DIM + MDIM) * AQ) {
        int r = idx / AQ, c = idx % AQ;
        g_Wcat[idx] = (c < 40) ? Wa[(size_t)r * 40 + c]
                               : Wq[(size_t)r * MDIM + (c - 40)];
    }
    if (idx < AQ)           g_bcat[idx] = (idx < 40) ? ba[idx] : bq[idx - 40];
    if (idx < G4)           g_bsum[idx] = bih[idx] + bhh[idx];
    if (idx < BATCH * DIM)  g_hidden[idx] = 0.f;       // h_{-1} = 0
    if (idx == 0)           g_barcnt = 0u;
}

// ---------------- SGEMM: C = A@B + bias. M%128==0, K%8==0, N%4==0 (guarded) ----------
__global__ void __launch_bounds__(256) sgemm_bias(
    const float* __restrict__ A, const float* __restrict__ B,
    const float* __restrict__ bias, float* __restrict__ C,
    int M, int N, int K) {
    __shared__ float As[8][128];
    __shared__ float Bs[8][128];
    int tid = threadIdx.x;
    int bm = blockIdx.x << 7;
    int bn = blockIdx.y << 7;
    int arow = tid >> 1,  ak   = (tid & 1) << 2;
    int brow = tid >> 5,  bcol = (tid & 31) << 2;
    int tx = (tid & 15) << 3, ty = ((tid >> 4) & 15) << 3;
    float acc[8][8];
#pragma unroll
    for (int i = 0; i < 8; ++i)
#pragma unroll
        for (int j = 0; j < 8; ++j) acc[i][j] = 0.f;
    const float* Aptr = A + (size_t)(bm + arow) * K + ak;
    for (int kt = 0; kt < K; kt += 8) {
        float4 av = *(const float4*)(Aptr + kt);
        As[ak + 0][arow] = av.x; As[ak + 1][arow] = av.y;
        As[ak + 2][arow] = av.z; As[ak + 3][arow] = av.w;
        float4 bv = make_float4(0.f, 0.f, 0.f, 0.f);
        if (bn + bcol < N) bv = *(const float4*)(B + (size_t)(kt + brow) * N + bn + bcol);
        *(float4*)&Bs[brow][bcol] = bv;
        __syncthreads();
#pragma unroll
        for (int k = 0; k < 8; ++k) {
            float ar[8], br[8];
            *(float4*)&ar[0] = *(float4*)&As[k][ty];
            *(float4*)&ar[4] = *(float4*)&As[k][ty + 4];
            *(float4*)&br[0] = *(float4*)&Bs[k][tx];
            *(float4*)&br[4] = *(float4*)&Bs[k][tx + 4];
#pragma unroll
            for (int i = 0; i < 8; ++i)
#pragma unroll
                for (int j = 0; j < 8; ++j) acc[i][j] = fmaf(ar[i], br[j], acc[i][j]);
        }
        __syncthreads();
    }
#pragma unroll
    for (int i = 0; i < 8; ++i) {
        size_t row = (size_t)(bm + ty + i);
#pragma unroll
        for (int j = 0; j < 8; j += 4) {
            int col = bn + tx + j;
            if (col < N) {
                float4 o;
                o.x = acc[i][j + 0] + bias[col + 0];
                o.y = acc[i][j + 1] + bias[col + 1];
                o.z = acc[i][j + 2] + bias[col + 2];
                o.w = acc[i][j + 3] + bias[col + 3];
                *(float4*)(C + row * N + col) = o;
            }
        }
    }
}

// ---------------- key normalization: unit-norm per group of 64 ----------------
__global__ void knorm_kernel(float* __restrict__ keys) {
    int w = (blockIdx.x << 3) + (threadIdx.x >> 5);   // 32768 groups
    int lane = threadIdx.x & 31;
    float* p = keys + (size_t)w * 64;
    float a = p[lane], b = p[lane + 32];
    float ss = a * a + b * b;
#pragma unroll
    for (int o = 16; o > 0; o >>= 1) ss += __shfl_xor_sync(0xffffffffu, ss, o);
    float inv = 1.f / fmaxf(sqrtf(ss), 1e-12f);
    p[lane] = a * inv; p[lane + 32] = b * inv;
}

// ---------------- persistent LSTM: 128 blocks, grid barrier per step ----------------
// block = 4 d-columns x 32 batches; thread (half,b,d) accumulates one K-half of the
// 4 gates for cell (b,d); half 0 applies the nonlinearity and holds c in a register.
__global__ void __launch_bounds__(256, 1) lstm_kernel() {
    extern __shared__ float sm[];
    float* h_s = sm;                 // 32 rows x 516 (padded)
    float* red = sm + 32 * 516;      // 128 cells x 4 partials
    int tid  = threadIdx.x;
    int half = tid >> 7;
    int ci   = tid & 127;
    int di   = ci & 3, b = ci >> 2;
    int d    = (blockIdx.x << 2) | di;
    int k0   = half << 8;
    const float4* wbase = (const float4*)(g_Wt + ((size_t)d * DIM + k0) * 4);
    float c = 0.f;
    for (int t = 0; t < SEQ; ++t) {
        const float4* hp4 = (const float4*)(g_hidden + (size_t)t * BATCH * DIM);
        for (int i = tid; i < BATCH * DIM / 4; i += 256) {
            int bb = i >> 7;
            int kk = (i & 127) << 2;
            *(float4*)&h_s[bb * 516 + kk] = hp4[i];
        }
        __syncthreads();
        float a0 = 0.f, a1 = 0.f, a2 = 0.f, a3 = 0.f;
        const float* hb = h_s + b * 516 + k0;
#pragma unroll 8
        for (int k = 0; k < 256; k += 4) {
            float4 hv = *(const float4*)(hb + k);
            float4 w0 = wbase[k + 0];
            float4 w1 = wbase[k + 1];
            float4 w2 = wbase[k + 2];
            float4 w3 = wbase[k + 3];
            a0 = fmaf(w0.x, hv.x, a0); a1 = fmaf(w0.y, hv.x, a1);
            a2 = fmaf(w0.z, hv.x, a2); a3 = fmaf(w0.w, hv.x, a3);
            a0 = fmaf(w1.x, hv.y, a0); a1 = fmaf(w1.y, hv.y, a1);
            a2 = fmaf(w1.z, hv.y, a2); a3 = fmaf(w1.w, hv.y, a3);
            a0 = fmaf(w2.x, hv.z, a0); a1 = fmaf(w2.y, hv.z, a1);
            a2 = fmaf(w2.z, hv.z, a2); a3 = fmaf(w2.w, hv.z, a3);
            a0 = fmaf(w3.x, hv.w, a0); a1 = fmaf(w3.y, hv.w, a1);
            a2 = fmaf(w3.z, hv.w, a2); a3 = fmaf(w3.w, hv.w, a3);
        }
        if (half) *(float4*)&red[ci * 4] = make_float4(a0, a1, a2, a3);
        __syncthreads();
        if (!half) {
            float4 r = *(float4*)&red[ci * 4];
            const float* gp = g_gates + ((size_t)t * BATCH + b) * G4;
            float gi = a0 + r.x + gp[0 * DIM + d];
            float gf = a1 + r.y + gp[1 * DIM + d];
            float gg = a2 + r.z + gp[2 * DIM + d];
            float go = a3 + r.w + gp[3 * DIM + d];
            c = sigf(gf) * c + sigf(gi) * tanhf(gg);
            float h = sigf(go) * tanhf(c);
            g_hidden[((size_t)(t + 1) * BATCH + b) * DIM + d] = h;
        }
        __threadfence();
        __syncthreads();
        if (tid == 0) {
            atomicAdd(&g_barcnt, 1u);
            unsigned target = (unsigned)(t + 1) * (unsigned)gridDim.x;
            while (*(volatile unsigned*)&g_barcnt < target) { }
        }
        __syncthreads();
        __threadfence();
    }
}

// ---------------- tape loop: 1 CTA per batch, 256 threads, all state in smem --------
// smem floats: tape 32x257, key 32x257, ro 256, act 296, rpos 128, wpos 128,
//              rd 16, wd 16, rw 8  => 17296 floats = 69184 B
__global__ void __launch_bounds__(256, 1) tape_kernel(float* __restrict__ out_tape) {
    extern __shared__ float ts[];
    float* s_tape = ts;                 // [l*257 + m]
    float* s_key  = ts + 8224;
    float* s_ro   = ts + 16448;
    float* s_act  = ts + 16704;
    float* s_rpos = ts + 17000;         // [tp*32 + l]
    float* s_wpos = ts + 17128;
    float* s_rd   = ts + 17256;         // [tp*4 + k]
    float* s_wd   = ts + 17272;
    float* s_rw   = ts + 17288;         // [tp*2 + k]

    int b = blockIdx.x;
    int tid = threadIdx.x;
    int tp = tid >> 6;                  // tape index of column m = tid

    for (int i = tid; i < 16448; i += 256) ts[i] = 0.f;   // tape + key
    s_ro[tid] = 0.f;
    if (tid < 128) {
        int tpp = tid >> 5, l = tid & 31;
        float v = (l == 0) ? 1.f : 0.f;
        s_rpos[tpp * 32 + l] = v;
        s_wpos[tpp * 32 + l] = v;
    }
    __syncthreads();

    const float* Wro = g_Wcat + (size_t)DIM * AQ;   // rows 512..767 of [Wa|Wq]

    for (int t = 0; t < SEQ; ++t) {
        // ---- (a) act = actq_h (precomputed, incl. bias) + ro @ Wro ----
        if (tid < 148) {
            const float2* aq2 = (const float2*)(g_actq + ((size_t)t * BATCH + b) * AQ);
            float2 a01 = aq2[tid];
            const float2* wrow = (const float2*)(Wro + 2 * tid);
#pragma unroll 8
            for (int r = 0; r < 256; ++r) {
                float rv = s_ro[r];
                float2 w = wrow[(size_t)r * (AQ / 2)];
                a01.x = fmaf(rv, w.x, a01.x);
                a01.y = fmaf(rv, w.y, a01.y);
            }
            s_act[2 * tid]     = a01.x;
            s_act[2 * tid + 1] = a01.y;
        }
        __syncthreads();
        // ---- (b) gates/dirs per tape ----
        if (tid < 4) {
            const float* ab = s_act + tid * 10;
            float m0 = fmaxf(fmaxf(ab[0], ab[1]), fmaxf(ab[2], ab[3]));
            float e0 = expf(ab[0] - m0), e1 = expf(ab[1] - m0);
            float e2 = expf(ab[2] - m0), e3 = expf(ab[3] - m0);
            float inv = 1.f / (e0 + e1 + e2 + e3);
            s_rd[tid * 4 + 0] = e0 * inv; s_rd[tid * 4 + 1] = e1 * inv;
            s_rd[tid * 4 + 2] = e2 * inv; s_rd[tid * 4 + 3] = e3 * inv;
            float n0 = fmaxf(fmaxf(ab[4], ab[5]), fmaxf(ab[6], ab[7]));
            float f0 = expf(ab[4] - n0), f1 = expf(ab[5] - n0);
            float f2 = expf(ab[6] - n0), f3 = expf(ab[7] - n0);
            float jnv = 1.f / (f0 + f1 + f2 + f3);
            s_wd[tid * 4 + 0] = f0 * jnv; s_wd[tid * 4 + 1] = f1 * jnv;
            s_wd[tid * 4 + 2] = f2 * jnv; s_wd[tid * 4 + 3] = f3 * jnv;
            s_rw[tid * 2 + 0] = sigf(ab[8]);
            s_rw[tid * 2 + 1] = sigf(ab[9]);
        }
        __syncthreads();
        // ---- (c) tape/key update + raw read (thread = column m) ----
        {
            int m = tid;
            float v  = g_values[((size_t)t * BATCH + b) * MDIM + m];
            float kk = g_keys  [((size_t)t * BATCH + b) * MDIM + m];
            float rw1 = s_rw[tp * 2 + 1];
            float ov = 0.f, ok = 0.f;
#pragma unroll
            for (int l = 0; l < 32; ++l) {
                float w = s_wpos[tp * 32 + l];
                ov = fmaf(s_tape[l * 257 + m], w, ov);
                ok = fmaf(s_key [l * 257 + m], w, ok);
            }
            float dv = (v - ov) * rw1;
            float dk = (kk - ok) * rw1;
            float ror = 0.f;
#pragma unroll
            for (int l = 0; l < 32; ++l) {
                float w = s_wpos[tp * 32 + l];
                float tv = s_tape[l * 257 + m] + w * dv;
                s_tape[l * 257 + m] = tv;
                ror = fmaf(tv, s_rpos[tp * 32 + l], ror);
                float kv = s_key[l * 257 + m] + w * dk;
                s_key[l * 257 + m] = kv;
            }
            float rog = ror * s_rw[tp * 2 + 0];
            s_ro[m] = rog;
            g_ro[((size_t)t * BATCH + b) * MDIM + m] = rog;
        }
        __syncthreads();
        // ---- (d)+(e) jpos + position updates (warp tpp, lane l) ----
        if (tid < 128) {
            int tpp = tid >> 5, l = tid & 31;
            const float* qp = s_act + 40 + tpp * 64;
            const float* kp = s_key + l * 257 + tpp * 64;
            float acc = 0.f;
#pragma unroll 8
            for (int c = 0; c < 64; ++c) acc = fmaf(kp[c], qp[c], acc);
            float ss = acc * acc;
#pragma unroll
            for (int o = 16; o > 0; o >>= 1) ss += __shfl_xor_sync(0xffffffffu, ss, o);
            float jp = acc / fmaxf(sqrtf(ss), 1e-12f);
            float rp   = s_rpos[tpp * 32 + l];
            float rprv = s_rpos[tpp * 32 + ((l + 1) & 31)];   // roll(rpos,-1)[l]
            float rnxt = s_rpos[tpp * 32 + ((l + 31) & 31)];  // roll(rpos,+1)[l]
            float wp   = s_wpos[tpp * 32 + l];
            float nwp = rprv * s_wd[tpp * 4 + 0] + wp * s_wd[tpp * 4 + 1]
                      + rnxt * s_wd[tpp * 4 + 2] + jp * s_wd[tpp * 4 + 3];
            float nrp = rprv * s_rd[tpp * 4 + 0] + rp * s_rd[tpp * 4 + 1]
                      + rnxt * s_rd[tpp * 4 + 2] + jp * s_rd[tpp * 4 + 3];
            __syncwarp();
            s_wpos[tpp * 32 + l] = nwp;
            s_rpos[tpp * 32 + l] = nrp;
        }
        __syncthreads();
    }
    // final tape -> out [l][b][m]
    for (int i = tid; i < 32 * MDIM; i += 256) {
        int l = i >> 8, m = i & 255;
        out_tape[(size_t)l * (BATCH * MDIM) + (size_t)b * MDIM + m] = s_tape[l * 257 + m];
    }
}

// ------------------------------- launch -------------------------------
extern "C" void kernel_launch(void* const* d_in, const int* in_sizes, int n_in,
                              void* d_out, int out_size) {
    const float* inputs = (const float*)d_in[0];
    const float* Wih    = (const float*)d_in[1];
    const float* Whh    = (const float*)d_in[2];
    const float* bih    = (const float*)d_in[3];
    const float* bhh    = (const float*)d_in[4];
    const float* Wa     = (const float*)d_in[5];
    const float* ba     = (const float*)d_in[6];
    const float* Wv     = (const float*)d_in[7];
    const float* bv     = (const float*)d_in[8];
    const float* Wk     = (const float*)d_in[9];
    const float* bk     = (const float*)d_in[10];
    const float* Wq     = (const float*)d_in[11];
    const float* bq     = (const float*)d_in[12];
    const float* Wo     = (const float*)d_in[13];
    const float* bo     = (const float*)d_in[14];
    float* out = (float*)d_out;

    float *p_gates, *p_hidden, *p_values, *p_keys, *p_actq, *p_ro, *p_bsum, *p_Wcat, *p_bcat;
    cudaGetSymbolAddress((void**)&p_gates,  g_gates);
    cudaGetSymbolAddress((void**)&p_hidden, g_hidden);
    cudaGetSymbolAddress((void**)&p_values, g_values);
    cudaGetSymbolAddress((void**)&p_keys,   g_keys);
    cudaGetSymbolAddress((void**)&p_actq,   g_actq);
    cudaGetSymbolAddress((void**)&p_ro,     g_ro);
    cudaGetSymbolAddress((void**)&p_bsum,   g_bsum);
    cudaGetSymbolAddress((void**)&p_Wcat,   g_Wcat);
    cudaGetSymbolAddress((void**)&p_bcat,   g_bcat);

    const int LSTM_SMEM = (32 * 516 + 128 * 4) * 4;   // 68096 B
    const int TAPE_SMEM = 17296 * 4;                  // 69184 B
    cudaFuncSetAttribute(lstm_kernel, cudaFuncAttributeMaxDynamicSharedMemorySize, LSTM_SMEM);
    cudaFuncSetAttribute(tape_kernel, cudaFuncAttributeMaxDynamicSharedMemorySize, TAPE_SMEM);

    init_kernel<<<4096, 256>>>(Whh, bih, bhh, Wa, ba, Wq, bq);
    // x @ Wih + (bih+bhh)
    sgemm_bias<<<dim3(64, 16), 256>>>(inputs, Wih, p_bsum, p_gates, ROWS, G4, DIM);
    // values / keys
    sgemm_bias<<<dim3(64, 2), 256>>>(inputs, Wv, bv, p_values, ROWS, MDIM, DIM);
    sgemm_bias<<<dim3(64, 2), 256>>>(inputs, Wk, bk, p_keys,   ROWS, MDIM, DIM);
    knorm_kernel<<<4096, 256>>>(p_keys);
    // LSTM recurrence
    lstm_kernel<<<128, 256, LSTM_SMEM>>>();
    // hidden @ [Wa|Wq] (h-part) + bias  -> actq
    sgemm_bias<<<dim3(64, 3), 256>>>(p_hidden + (size_t)BATCH * DIM, p_Wcat, p_bcat,
                                     p_actq, ROWS, AQ, DIM);
    // tape recurrence (writes g_ro and the final-tape section of d_out)
    tape_kernel<<<32, 256, TAPE_SMEM>>>(out + (size_t)ROWS * DIM);
    // read_outs @ Wo + bo -> outputs
    sgemm_bias<<<dim3(64, 4), 256>>>(p_ro, Wo, bo, out, ROWS, DIM, MDIM);
}

// round 10
// speedup vs baseline: 1.9263x; 1.9263x over previous
#include <cuda_runtime.h>
#include <math.h>

#define SEQ   256
#define BATCH 32
#define DIM   512
#define MDIM  256            // N_TAPES*HEAD_DIM
#define G4    2048           // 4*DIM
#define AQ    296            // 40 action + 256 query
#define AQ2   148
#define ROWS  8192           // SEQ*BATCH

typedef unsigned long long ull;

// ---------------- device scratch ----------------
__device__ float g_gates [(size_t)ROWS * G4];
__device__ float g_hidden[(size_t)(SEQ + 1) * BATCH * DIM];
__device__ float g_values[(size_t)ROWS * MDIM];
__device__ float g_keys  [(size_t)ROWS * MDIM];
__device__ float g_actq  [(size_t)ROWS * AQ];
__device__ float g_ro    [(size_t)ROWS * MDIM];
__device__ float g_Wt    [(size_t)DIM * DIM * 4];   // [bd][k][di][gate]
__device__ float g_Wcat  [(size_t)(DIM + MDIM) * AQ];
__device__ float g_bcat  [AQ];
__device__ float g_bsum  [G4];
__device__ unsigned g_arrive[128];
__device__ unsigned g_go;

__device__ __forceinline__ float sigf(float x) { return 1.f / (1.f + expf(-x)); }

// ---- packed fp32x2 helpers (Blackwell FFMA2 via PTX) ----
__device__ __forceinline__ ull fma2(ull a, ull b, ull c) {
    ull d; asm("fma.rn.f32x2 %0, %1, %2, %3;" : "=l"(d) : "l"(a), "l"(b), "l"(c));
    return d;
}
__device__ __forceinline__ ull add2(ull a, ull b) {
    ull d; asm("add.rn.f32x2 %0, %1, %2;" : "=l"(d) : "l"(a), "l"(b));
    return d;
}
__device__ __forceinline__ ull packdup(float x) {
    ull d; asm("mov.b64 %0, {%1, %1};" : "=l"(d) : "f"(x));
    return d;
}
__device__ __forceinline__ float2 unpack2(ull v) {
    float2 r; asm("mov.b64 {%0, %1}, %2;" : "=f"(r.x), "=f"(r.y) : "l"(v));
    return r;
}
__device__ __forceinline__ void st_rel(unsigned* p, unsigned v) {
    asm volatile("st.release.gpu.u32 [%0], %1;" :: "l"(p), "r"(v) : "memory");
}
__device__ __forceinline__ unsigned ld_acq(const unsigned* p) {
    unsigned v; asm volatile("ld.acquire.gpu.u32 %0, [%1];" : "=r"(v) : "l"(p) : "memory");
    return v;
}

// ---------------- init ----------------
__global__ void init_kernel(const float* __restrict__ Whh,
                            const float* __restrict__ bih, const float* __restrict__ bhh,
                            const float* __restrict__ Wa,  const float* __restrict__ ba,
                            const float* __restrict__ Wq,  const float* __restrict__ bq) {
    int idx = blockIdx.x * blockDim.x + threadIdx.x;
    if (idx < DIM * DIM * 4) {
        int g  = idx & 3;
        int di = (idx >> 2) & 3;
        int k  = (idx >> 4) & (DIM - 1);
        int bd = idx >> 13;
        g_Wt[idx] = Whh[(size_t)k * G4 + g * DIM + bd * 4 + di];
    }
    if (idx < (DIM + MDIM) * AQ) {
        int r = idx / AQ, c = idx % AQ;
        g_Wcat[idx] = (c < 40) ? Wa[(size_t)r * 40 + c]
                               : Wq[(size_t)r * MDIM + (c - 40)];
    }
    if (idx < AQ)           g_bcat[idx] = (idx < 40) ? ba[idx] : bq[idx - 40];
    if (idx < G4)           g_bsum[idx] = bih[idx] + bhh[idx];
    if (idx < BATCH * DIM)  g_hidden[idx] = 0.f;
    if (idx < 128)          g_arrive[idx] = 0u;
    if (idx == 0)           g_go = 0u;
}

// ---------------- SGEMM (f32x2): C = A@B + bias ----------------
__global__ void __launch_bounds__(256) sgemm_bias(
    const float* __restrict__ A, const float* __restrict__ B,
    const float* __restrict__ bias, float* __restrict__ C,
    int M, int N, int K) {
    __shared__ float As[8][128];
    __shared__ float Bs[8][128];
    int tid = threadIdx.x;
    int bm = blockIdx.x << 7;
    int bn = blockIdx.y << 7;
    int arow = tid >> 1,  ak   = (tid & 1) << 2;
    int brow = tid >> 5,  bcol = (tid & 31) << 2;
    int tx = (tid & 15) << 3, ty = ((tid >> 4) & 15) << 3;
    ull acc2[8][4];
#pragma unroll
    for (int i = 0; i < 8; ++i)
#pragma unroll
        for (int j = 0; j < 4; ++j) acc2[i][j] = 0ULL;
    const float* Aptr = A + (size_t)(bm + arow) * K + ak;
    for (int kt = 0; kt < K; kt += 8) {
        float4 av = *(const float4*)(Aptr + kt);
        As[ak + 0][arow] = av.x; As[ak + 1][arow] = av.y;
        As[ak + 2][arow] = av.z; As[ak + 3][arow] = av.w;
        float4 bv = make_float4(0.f, 0.f, 0.f, 0.f);
        if (bn + bcol < N) bv = *(const float4*)(B + (size_t)(kt + brow) * N + bn + bcol);
        *(float4*)&Bs[brow][bcol] = bv;
        __syncthreads();
#pragma unroll
        for (int k = 0; k < 8; ++k) {
            float ar[8];
            *(float4*)&ar[0] = *(float4*)&As[k][ty];
            *(float4*)&ar[4] = *(float4*)&As[k][ty + 4];
            const ull* bp = (const ull*)&Bs[k][tx];
            ull b2[4];
            b2[0] = bp[0]; b2[1] = bp[1]; b2[2] = bp[2]; b2[3] = bp[3];
#pragma unroll
            for (int i = 0; i < 8; ++i) {
                ull ad = packdup(ar[i]);
#pragma unroll
                for (int jp = 0; jp < 4; ++jp)
                    acc2[i][jp] = fma2(ad, b2[jp], acc2[i][jp]);
            }
        }
        __syncthreads();
    }
#pragma unroll
    for (int i = 0; i < 8; ++i) {
        size_t row = (size_t)(bm + ty + i);
#pragma unroll
        for (int jp = 0; jp < 4; ++jp) {
            int col = bn + tx + 2 * jp;
            if (col < N) {
                float2 p = unpack2(acc2[i][jp]);
                float2 o;
                o.x = p.x + bias[col];
                o.y = p.y + bias[col + 1];
                *(float2*)(C + row * N + col) = o;
            }
        }
    }
}

// ---------------- key normalization ----------------
__global__ void knorm_kernel(float* __restrict__ keys) {
    int w = (blockIdx.x << 3) + (threadIdx.x >> 5);
    int lane = threadIdx.x & 31;
    float* p = keys + (size_t)w * 64;
    float a = p[lane], b = p[lane + 32];
    float ss = a * a + b * b;
#pragma unroll
    for (int o = 16; o > 0; o >>= 1) ss += __shfl_xor_sync(0xffffffffu, ss, o);
    float inv = 1.f / fmaxf(sqrtf(ss), 1e-12f);
    p[lane] = a * inv; p[lane + 32] = b * inv;
}

// ---------------- persistent LSTM: smem weights + flag barrier + f32x2 ----------------
__global__ void __launch_bounds__(256, 1) lstm_kernel() {
    extern __shared__ float sm[];
    float* h_s = sm;                      // 32 x 516
    float* w_s = sm + 16512;              // 512 x 16  [k][di*4+g]
    ull*   red = (ull*)(sm + 24704);      // 128 cells x 2 ull
    int tid  = threadIdx.x;
    int half = tid >> 7;
    int ci   = tid & 127;
    int di   = ci & 3, b = ci >> 2;
    int bd   = blockIdx.x;
    int d    = (bd << 2) | di;
    int k0   = half << 8;

    // load this block's weight slice once (contiguous, coalesced)
    {
        const float4* wg = (const float4*)(g_Wt + (size_t)bd * 8192);
        float4* ws4 = (float4*)w_s;
        for (int i = tid; i < 2048; i += 256) ws4[i] = wg[i];
    }
    const ull* wp = (const ull*)(w_s + (size_t)k0 * 16 + di * 4);  // wp[k*8], wp[k*8+1]
    float c = 0.f;

    for (int t = 0; t < SEQ; ++t) {
        // stage h_{t-1} into smem
        const float4* hp4 = (const float4*)(g_hidden + (size_t)t * BATCH * DIM);
        for (int i = tid; i < 4096; i += 256) {
            int bb = i >> 7;
            int kk = (i & 127) << 2;
            *(float4*)&h_s[bb * 516 + kk] = hp4[i];
        }
        __syncthreads();
        ull a01 = 0ULL, a23 = 0ULL;
        const float* hb = h_s + b * 516 + k0;
#pragma unroll 4
        for (int k = 0; k < 256; k += 4) {
            float4 hv = *(const float4*)(hb + k);
            ull h0 = packdup(hv.x), h1 = packdup(hv.y);
            ull h2 = packdup(hv.z), h3 = packdup(hv.w);
            a01 = fma2(h0, wp[(k + 0) * 8 + 0], a01);
            a23 = fma2(h0, wp[(k + 0) * 8 + 1], a23);
            a01 = fma2(h1, wp[(k + 1) * 8 + 0], a01);
            a23 = fma2(h1, wp[(k + 1) * 8 + 1], a23);
            a01 = fma2(h2, wp[(k + 2) * 8 + 0], a01);
            a23 = fma2(h2, wp[(k + 2) * 8 + 1], a23);
            a01 = fma2(h3, wp[(k + 3) * 8 + 0], a01);
            a23 = fma2(h3, wp[(k + 3) * 8 + 1], a23);
        }
        if (half) { red[ci * 2] = a01; red[ci * 2 + 1] = a23; }
        __syncthreads();
        if (!half) {
            float2 r01 = unpack2(red[ci * 2]), r23 = unpack2(red[ci * 2 + 1]);
            float2 m01 = unpack2(a01),         m23 = unpack2(a23);
            const float* gp = g_gates + ((size_t)t * BATCH + b) * G4;
            float gi = m01.x + r01.x + gp[0 * DIM + d];
            float gf = m01.y + r01.y + gp[1 * DIM + d];
            float gg = m23.x + r23.x + gp[2 * DIM + d];
            float go = m23.y + r23.y + gp[3 * DIM + d];
            c = sigf(gf) * c + sigf(gi) * tanhf(gg);
            float h = sigf(go) * tanhf(c);
            g_hidden[((size_t)(t + 1) * BATCH + b) * DIM + d] = h;
        }
        __syncthreads();
        // flag-based grid barrier (release/acquire, no atomics)
        if (tid == 0) st_rel(&g_arrive[bd], (unsigned)(t + 1));
        if (bd == 0) {
            if (tid < 128) while (ld_acq(&g_arrive[tid]) < (unsigned)(t + 1)) {}
            __syncthreads();
            if (tid == 0) st_rel(&g_go, (unsigned)(t + 1));
        } else {
            if (tid == 0) while (ld_acq(&g_go) < (unsigned)(t + 1)) {}
            __syncthreads();
        }
    }
}

// ---------------- tape loop: 1 CTA/batch, 512 threads ----------------
// smem floats: tape 8224 | key 8224 | ro 256 | act 296 | pa 592 | pov 512 |
//              pok 512 | pror 512 | rpos 128 | wpos 128 | rd 16 | wd 16 | rw 8
__global__ void __launch_bounds__(512, 1) tape_kernel(float* __restrict__ out_tape) {
    extern __shared__ float ts[];
    float* s_tape = ts;
    float* s_key  = ts + 8224;
    float* s_ro   = ts + 16448;
    float* s_act  = ts + 16704;
    ull*   s_pa   = (ull*)(ts + 17000);   // [h*148 + j]
    float* s_pov  = ts + 17592;
    float* s_pok  = ts + 18104;
    float* s_pror = ts + 18616;
    float* s_rpos = ts + 19128;
    float* s_wpos = ts + 19256;
    float* s_rd   = ts + 19384;
    float* s_wd   = ts + 19400;
    float* s_rw   = ts + 19416;

    int b   = blockIdx.x;
    int tid = threadIdx.x;
    int m   = tid & 255;
    int seg = tid >> 8;
    int tp  = m >> 6;
    int l0  = seg << 4;

    for (int i = tid; i < 16448; i += 512) ts[i] = 0.f;
    if (tid < 256) s_ro[tid] = 0.f;
    if (tid < 128) {
        int tpp = tid >> 5, l = tid & 31;
        float v = (l == 0) ? 1.f : 0.f;
        s_rpos[tpp * 32 + l] = v;
        s_wpos[tpp * 32 + l] = v;
    }
    __syncthreads();

    const ull* WroT = (const ull*)(g_Wcat + (size_t)DIM * AQ);  // [r][148] as ull pairs

    for (int t = 0; t < SEQ; ++t) {
        // ---- (a) act partials: thread (h=seg, j=m) over r in [h*128, h*128+128) ----
        if (m < AQ2) {
            int j = m;
            ull acc0, acc1 = 0ULL;
            if (seg == 0) {
                acc0 = *(const ull*)(g_actq + ((size_t)t * BATCH + b) * AQ + 2 * j);
            } else acc0 = 0ULL;
            int rb = seg << 7;
            const ull* wr = WroT + (size_t)rb * AQ2 + j;
#pragma unroll 8
            for (int r = 0; r < 128; r += 2) {
                ull d0 = packdup(s_ro[rb + r]);
                ull d1 = packdup(s_ro[rb + r + 1]);
                acc0 = fma2(d0, wr[(size_t)r * AQ2], acc0);
                acc1 = fma2(d1, wr[(size_t)(r + 1) * AQ2], acc1);
            }
            s_pa[seg * AQ2 + j] = add2(acc0, acc1);
        }
        __syncthreads();
        if (tid < AQ2) {
            float2 v = unpack2(add2(s_pa[tid], s_pa[AQ2 + tid]));
            s_act[2 * tid]     = v.x;
            s_act[2 * tid + 1] = v.y;
        }
        __syncthreads();
        // ---- (b) softmaxes + gates per tape ----
        if (tid < 4) {
            const float* ab = s_act + tid * 10;
            float m0 = fmaxf(fmaxf(ab[0], ab[1]), fmaxf(ab[2], ab[3]));
            float e0 = expf(ab[0] - m0), e1 = expf(ab[1] - m0);
            float e2 = expf(ab[2] - m0), e3 = expf(ab[3] - m0);
            float inv = 1.f / (e0 + e1 + e2 + e3);
            s_rd[tid * 4 + 0] = e0 * inv; s_rd[tid * 4 + 1] = e1 * inv;
            s_rd[tid * 4 + 2] = e2 * inv; s_rd[tid * 4 + 3] = e3 * inv;
            float n0 = fmaxf(fmaxf(ab[4], ab[5]), fmaxf(ab[6], ab[7]));
            float f0 = expf(ab[4] - n0), f1 = expf(ab[5] - n0);
            float f2 = expf(ab[6] - n0), f3 = expf(ab[7] - n0);
            float jnv = 1.f / (f0 + f1 + f2 + f3);
            s_wd[tid * 4 + 0] = f0 * jnv; s_wd[tid * 4 + 1] = f1 * jnv;
            s_wd[tid * 4 + 2] = f2 * jnv; s_wd[tid * 4 + 3] = f3 * jnv;
            s_rw[tid * 2 + 0] = sigf(ab[8]);
            s_rw[tid * 2 + 1] = sigf(ab[9]);
        }
        __syncthreads();
        // ---- (c) tape/key update, l-range split across 2 segments ----
        {
            float v  = g_values[((size_t)t * BATCH + b) * MDIM + m];
            float kk = g_keys  [((size_t)t * BATCH + b) * MDIM + m];
            float ovp = 0.f, okp = 0.f;
#pragma unroll
            for (int l = l0; l < l0 + 16; ++l) {
                float w = s_wpos[tp * 32 + l];
                ovp = fmaf(s_tape[l * 257 + m], w, ovp);
                okp = fmaf(s_key [l * 257 + m], w, okp);
            }
            s_pov[seg * 256 + m] = ovp;
            s_pok[seg * 256 + m] = okp;
            __syncthreads();
            float rw1 = s_rw[tp * 2 + 1];
            float dv = (v  - (s_pov[m] + s_pov[256 + m])) * rw1;
            float dk = (kk - (s_pok[m] + s_pok[256 + m])) * rw1;
            float rorp = 0.f;
#pragma unroll
            for (int l = l0; l < l0 + 16; ++l) {
                float w = s_wpos[tp * 32 + l];
                float tv = s_tape[l * 257 + m] + w * dv;
                s_tape[l * 257 + m] = tv;
                rorp = fmaf(tv, s_rpos[tp * 32 + l], rorp);
                s_key[l * 257 + m] = s_key[l * 257 + m] + w * dk;
            }
            s_pror[seg * 256 + m] = rorp;
        }
        __syncthreads();
        if (tid < 256) {
            float rog = (s_pror[m] + s_pror[256 + m]) * s_rw[tp * 2 + 0];
            s_ro[m] = rog;
            g_ro[((size_t)t * BATCH + b) * MDIM + m] = rog;
        }
        // ---- (d) jpos + position updates ----
        if (tid < 128) {
            int tpp = tid >> 5, l = tid & 31;
            const float* qp = s_act + 40 + tpp * 64;
            const float* kp = s_key + l * 257 + tpp * 64;
            float acc = 0.f;
#pragma unroll 8
            for (int cc = 0; cc < 64; ++cc) acc = fmaf(kp[cc], qp[cc], acc);
            float ss = acc * acc;
#pragma unroll
            for (int o = 16; o > 0; o >>= 1) ss += __shfl_xor_sync(0xffffffffu, ss, o);
            float jp = acc / fmaxf(sqrtf(ss), 1e-12f);
            float rp   = s_rpos[tpp * 32 + l];
            float rprv = s_rpos[tpp * 32 + ((l + 1) & 31)];
            float rnxt = s_rpos[tpp * 32 + ((l + 31) & 31)];
            float wp   = s_wpos[tpp * 32 + l];
            float nwp = rprv * s_wd[tpp * 4 + 0] + wp * s_wd[tpp * 4 + 1]
                      + rnxt * s_wd[tpp * 4 + 2] + jp * s_wd[tpp * 4 + 3];
            float nrp = rprv * s_rd[tpp * 4 + 0] + rp * s_rd[tpp * 4 + 1]
                      + rnxt * s_rd[tpp * 4 + 2] + jp * s_rd[tpp * 4 + 3];
            __syncwarp();
            s_wpos[tpp * 32 + l] = nwp;
            s_rpos[tpp * 32 + l] = nrp;
        }
        __syncthreads();
    }
    for (int i = tid; i < 32 * MDIM; i += 512) {
        int l = i >> 8, mm = i & 255;
        out_tape[(size_t)l * (BATCH * MDIM) + (size_t)b * MDIM + mm] = s_tape[l * 257 + mm];
    }
}

// ------------------------------- launch -------------------------------
extern "C" void kernel_launch(void* const* d_in, const int* in_sizes, int n_in,
                              void* d_out, int out_size) {
    const float* inputs = (const float*)d_in[0];
    const float* Wih    = (const float*)d_in[1];
    const float* Whh    = (const float*)d_in[2];
    const float* bih    = (const float*)d_in[3];
    const float* bhh    = (const float*)d_in[4];
    const float* Wa     = (const float*)d_in[5];
    const float* ba     = (const float*)d_in[6];
    const float* Wv     = (const float*)d_in[7];
    const float* bv     = (const float*)d_in[8];
    const float* Wk     = (const float*)d_in[9];
    const float* bk     = (const float*)d_in[10];
    const float* Wq     = (const float*)d_in[11];
    const float* bq     = (const float*)d_in[12];
    const float* Wo     = (const float*)d_in[13];
    const float* bo     = (const float*)d_in[14];
    float* out = (float*)d_out;

    float *p_gates, *p_hidden, *p_values, *p_keys, *p_actq, *p_ro, *p_bsum, *p_Wcat, *p_bcat;
    cudaGetSymbolAddress((void**)&p_gates,  g_gates);
    cudaGetSymbolAddress((void**)&p_hidden, g_hidden);
    cudaGetSymbolAddress((void**)&p_values, g_values);
    cudaGetSymbolAddress((void**)&p_keys,   g_keys);
    cudaGetSymbolAddress((void**)&p_actq,   g_actq);
    cudaGetSymbolAddress((void**)&p_ro,     g_ro);
    cudaGetSymbolAddress((void**)&p_bsum,   g_bsum);
    cudaGetSymbolAddress((void**)&p_Wcat,   g_Wcat);
    cudaGetSymbolAddress((void**)&p_bcat,   g_bcat);

    const int LSTM_SMEM = (16512 + 8192 + 512) * 4;   // 100,864 B
    const int TAPE_SMEM = 19424 * 4;                  // 77,696 B
    cudaFuncSetAttribute(lstm_kernel, cudaFuncAttributeMaxDynamicSharedMemorySize, LSTM_SMEM);
    cudaFuncSetAttribute(tape_kernel, cudaFuncAttributeMaxDynamicSharedMemorySize, TAPE_SMEM);

    init_kernel<<<4096, 256>>>(Whh, bih, bhh, Wa, ba, Wq, bq);
    sgemm_bias<<<dim3(64, 16), 256>>>(inputs, Wih, p_bsum, p_gates, ROWS, G4, DIM);
    sgemm_bias<<<dim3(64, 2), 256>>>(inputs, Wv, bv, p_values, ROWS, MDIM, DIM);
    sgemm_bias<<<dim3(64, 2), 256>>>(inputs, Wk, bk, p_keys,   ROWS, MDIM, DIM);
    knorm_kernel<<<4096, 256>>>(p_keys);
    lstm_kernel<<<128, 256, LSTM_SMEM>>>();
    sgemm_bias<<<dim3(64, 3), 256>>>(p_hidden + (size_t)BATCH * DIM, p_Wcat, p_bcat,
                                     p_actq, ROWS, AQ, DIM);
    tape_kernel<<<32, 512, TAPE_SMEM>>>(out + (size_t)ROWS * DIM);
    sgemm_bias<<<dim3(64, 4), 256>>>(p_ro, Wo, bo, out, ROWS, DIM, MDIM);
}

// round 11
// speedup vs baseline: 2.0096x; 1.0433x over previous
#include <cuda_runtime.h>
#include <math.h>

#define SEQ    256
#define BATCH  32
#define DIM    512
#define MDIM   256            // N_TAPES*HEAD_DIM
#define NFRONT 2560           // 4*DIM (gates) + MDIM (values) + MDIM (keys)
#define AQ     296            // 40 action + 256 query
#define AQ2    148
#define ROWS   8192           // SEQ*BATCH

typedef unsigned long long ull;

// ---------------- device scratch ----------------
__device__ float g_front [(size_t)ROWS * NFRONT];          // [gates | values | keys]
__device__ float g_hidden[(size_t)(SEQ + 1) * BATCH * DIM];
__device__ float g_actq  [(size_t)ROWS * AQ];
__device__ float g_ro    [(size_t)ROWS * MDIM];
__device__ float g_Wt    [(size_t)DIM * DIM * 4];          // [bd][k][di][gate]
__device__ float g_Wfront[(size_t)DIM * NFRONT];           // [Wih | Wv | Wk]
__device__ float g_bfront[NFRONT];
__device__ float g_Wcat  [(size_t)DIM * AQ];               // h-part of [Wa|Wq]
__device__ float g_bcat  [AQ];
__device__ __align__(16) ull g_WroP[(size_t)128 * AQ2 * 2];// [r2][j] -> (w[2r2][2j:2j+2], w[2r2+1][2j:2j+2])
__device__ unsigned g_arrive[128];
__device__ unsigned g_go;

__device__ __forceinline__ float sigf(float x) { return 1.f / (1.f + expf(-x)); }

// ---- packed fp32x2 helpers ----
__device__ __forceinline__ ull fma2(ull a, ull b, ull c) {
    ull d; asm("fma.rn.f32x2 %0, %1, %2, %3;" : "=l"(d) : "l"(a), "l"(b), "l"(c));
    return d;
}
__device__ __forceinline__ ull add2(ull a, ull b) {
    ull d; asm("add.rn.f32x2 %0, %1, %2;" : "=l"(d) : "l"(a), "l"(b));
    return d;
}
__device__ __forceinline__ ull packdup(float x) {
    ull d; asm("mov.b64 %0, {%1, %1};" : "=l"(d) : "f"(x));
    return d;
}
__device__ __forceinline__ ull pack2(float x, float y) {
    ull d; asm("mov.b64 %0, {%1, %2};" : "=l"(d) : "f"(x), "f"(y));
    return d;
}
__device__ __forceinline__ float2 unpack2(ull v) {
    float2 r; asm("mov.b64 {%0, %1}, %2;" : "=f"(r.x), "=f"(r.y) : "l"(v));
    return r;
}
__device__ __forceinline__ void st_rel(unsigned* p, unsigned v) {
    asm volatile("st.release.gpu.u32 [%0], %1;" :: "l"(p), "r"(v) : "memory");
}
__device__ __forceinline__ unsigned ld_acq(const unsigned* p) {
    unsigned v; asm volatile("ld.acquire.gpu.u32 %0, [%1];" : "=r"(v) : "l"(p) : "memory");
    return v;
}

// ---------------- init ----------------
__global__ void init_kernel(const float* __restrict__ Whh,
                            const float* __restrict__ bih, const float* __restrict__ bhh,
                            const float* __restrict__ Wa,  const float* __restrict__ ba,
                            const float* __restrict__ Wq,  const float* __restrict__ bq,
                            const float* __restrict__ Wih, const float* __restrict__ Wv,
                            const float* __restrict__ bv,  const float* __restrict__ Wk,
                            const float* __restrict__ bk) {
    int idx = blockIdx.x * blockDim.x + threadIdx.x;   // grid covers 1,310,720
    if (idx < DIM * DIM * 4) {
        int g  = idx & 3;
        int di = (idx >> 2) & 3;
        int k  = (idx >> 4) & (DIM - 1);
        int bd = idx >> 13;
        g_Wt[idx] = Whh[(size_t)k * (4 * DIM) + g * DIM + bd * 4 + di];
    }
    if (idx < DIM * NFRONT) {
        int r = idx / NFRONT, c = idx % NFRONT;
        float w;
        if (c < 2048)      w = Wih[(size_t)r * 2048 + c];
        else if (c < 2304) w = Wv[(size_t)r * MDIM + (c - 2048)];
        else               w = Wk[(size_t)r * MDIM + (c - 2304)];
        g_Wfront[idx] = w;
    }
    if (idx < NFRONT) {
        g_bfront[idx] = (idx < 2048) ? (bih[idx] + bhh[idx])
                      : (idx < 2304) ? bv[idx - 2048] : bk[idx - 2304];
    }
    if (idx < DIM * AQ) {
        int r = idx / AQ, c = idx % AQ;
        g_Wcat[idx] = (c < 40) ? Wa[(size_t)r * 40 + c]
                               : Wq[(size_t)r * MDIM + (c - 40)];
    }
    if (idx < AQ) g_bcat[idx] = (idx < 40) ? ba[idx] : bq[idx - 40];
    if (idx < 128 * AQ2) {
        int r2 = idx / AQ2, j = idx % AQ2;
        int c0 = 2 * j, c1 = 2 * j + 1;
        int ra = 512 + 2 * r2, rb = ra + 1;
        float a0 = (c0 < 40) ? Wa[(size_t)ra * 40 + c0] : Wq[(size_t)ra * MDIM + c0 - 40];
        float a1 = (c1 < 40) ? Wa[(size_t)ra * 40 + c1] : Wq[(size_t)ra * MDIM + c1 - 40];
        float b0 = (c0 < 40) ? Wa[(size_t)rb * 40 + c0] : Wq[(size_t)rb * MDIM + c0 - 40];
        float b1 = (c1 < 40) ? Wa[(size_t)rb * 40 + c1] : Wq[(size_t)rb * MDIM + c1 - 40];
        g_WroP[(size_t)idx * 2]     = pack2(a0, a1);
        g_WroP[(size_t)idx * 2 + 1] = pack2(b0, b1);
    }
    if (idx < BATCH * DIM) g_hidden[idx] = 0.f;
    if (idx < 128)         g_arrive[idx] = 0u;
    if (idx == 0)          g_go = 0u;
}

// ---------------- double-buffered SGEMM (f32x2): C = A@B + bias ----------------
__global__ void __launch_bounds__(256, 2) sgemm_bias(
    const float* __restrict__ A, const float* __restrict__ B,
    const float* __restrict__ bias, float* __restrict__ C,
    int M, int N, int K) {
    __shared__ float As[2][8][128];
    __shared__ float Bs[2][8][128];
    int tid = threadIdx.x;
    int bm = blockIdx.x << 7;
    int bn = blockIdx.y << 7;
    int arow = tid >> 1,  ak   = (tid & 1) << 2;
    int brow = tid >> 5,  bcol = (tid & 31) << 2;
    int tx = (tid & 15) << 3, ty = ((tid >> 4) & 15) << 3;
    ull acc2[8][4];
#pragma unroll
    for (int i = 0; i < 8; ++i)
#pragma unroll
        for (int j = 0; j < 4; ++j) acc2[i][j] = 0ULL;
    const float* Aptr = A + (size_t)(bm + arow) * K + ak;
    const float* Bptr = B + (size_t)brow * N + bn + bcol;
    bool bok = (bn + bcol) < N;
    // preload slab 0
    {
        float4 av = *(const float4*)(Aptr);
        float4 bv = bok ? *(const float4*)(Bptr) : make_float4(0.f, 0.f, 0.f, 0.f);
        As[0][ak + 0][arow] = av.x; As[0][ak + 1][arow] = av.y;
        As[0][ak + 2][arow] = av.z; As[0][ak + 3][arow] = av.w;
        *(float4*)&Bs[0][brow][bcol] = bv;
    }
    __syncthreads();
    int buf = 0;
    for (int kt = 0; kt < K; kt += 8) {
        bool more = (kt + 8) < K;
        float4 av2, bv2;
        if (more) {
            av2 = *(const float4*)(Aptr + kt + 8);
            bv2 = bok ? *(const float4*)(Bptr + (size_t)(kt + 8) * N)
                      : make_float4(0.f, 0.f, 0.f, 0.f);
        }
#pragma unroll
        for (int k = 0; k < 8; ++k) {
            float ar[8];
            *(float4*)&ar[0] = *(float4*)&As[buf][k][ty];
            *(float4*)&ar[4] = *(float4*)&As[buf][k][ty + 4];
            const ull* bp = (const ull*)&Bs[buf][k][tx];
            ull b2[4];
            b2[0] = bp[0]; b2[1] = bp[1]; b2[2] = bp[2]; b2[3] = bp[3];
#pragma unroll
            for (int i = 0; i < 8; ++i) {
                ull ad = packdup(ar[i]);
#pragma unroll
                for (int jp = 0; jp < 4; ++jp)
                    acc2[i][jp] = fma2(ad, b2[jp], acc2[i][jp]);
            }
        }
        if (more) {
            int nb = buf ^ 1;
            As[nb][ak + 0][arow] = av2.x; As[nb][ak + 1][arow] = av2.y;
            As[nb][ak + 2][arow] = av2.z; As[nb][ak + 3][arow] = av2.w;
            *(float4*)&Bs[nb][brow][bcol] = bv2;
            __syncthreads();
            buf = nb;
        }
    }
#pragma unroll
    for (int i = 0; i < 8; ++i) {
        size_t row = (size_t)(bm + ty + i);
#pragma unroll
        for (int jp = 0; jp < 4; ++jp) {
            int col = bn + tx + 2 * jp;
            if (col < N) {
                float2 p = unpack2(acc2[i][jp]);
                float2 o;
                o.x = p.x + bias[col];
                o.y = p.y + bias[col + 1];
                *(float2*)(C + row * N + col) = o;
            }
        }
    }
}

// ---------------- key normalization on fused buffer (cols 2304..2559) ----------------
__global__ void knorm_kernel() {
    int w = (blockIdx.x << 3) + (threadIdx.x >> 5);   // 32768 groups
    int lane = threadIdx.x & 31;
    int rr = w >> 2, tp = w & 3;
    float* p = g_front + (size_t)rr * NFRONT + 2304 + tp * 64;
    float a = p[lane], b = p[lane + 32];
    float ss = a * a + b * b;
#pragma unroll
    for (int o = 16; o > 0; o >>= 1) ss += __shfl_xor_sync(0xffffffffu, ss, o);
    float inv = 1.f / fmaxf(sqrtf(ss), 1e-12f);
    p[lane] = a * inv; p[lane + 32] = b * inv;
}

// ---------------- persistent LSTM ----------------
__global__ void __launch_bounds__(256, 1) lstm_kernel() {
    extern __shared__ float sm[];
    float* h_s = sm;                      // 32 x 516
    float* w_s = sm + 16512;              // 512 x 16  [k][di*4+g]
    ull*   red = (ull*)(sm + 24704);      // 128 cells x 2 ull
    int tid  = threadIdx.x;
    int half = tid >> 7;
    int ci   = tid & 127;
    int di   = ci & 3, b = ci >> 2;
    int bd   = blockIdx.x;
    int d    = (bd << 2) | di;
    int k0   = half << 8;

    {   // weight slice once, coalesced
        const float4* wg = (const float4*)(g_Wt + (size_t)bd * 8192);
        float4* ws4 = (float4*)w_s;
        for (int i = tid; i < 2048; i += 256) ws4[i] = wg[i];
    }
    const ulonglong2* wp2 = ((const ulonglong2*)w_s) + (size_t)k0 * 4 + di;
    float c = 0.f;

    for (int t = 0; t < SEQ; ++t) {
        // prefetch DRAM-resident gate precomputes early (half 0 uses them)
        const float* gp = g_front + ((size_t)t * BATCH + b) * NFRONT + d;
        float pg0 = 0.f, pg1 = 0.f, pg2 = 0.f, pg3 = 0.f;
        if (!half) {
            pg0 = __ldg(gp);
            pg1 = __ldg(gp + 512);
            pg2 = __ldg(gp + 1024);
            pg3 = __ldg(gp + 1536);
        }
        // stage h_{t-1}
        const float4* hp4 = (const float4*)(g_hidden + (size_t)t * BATCH * DIM);
        for (int i = tid; i < 4096; i += 256) {
            int bb = i >> 7;
            int kk = (i & 127) << 2;
            *(float4*)&h_s[bb * 516 + kk] = hp4[i];
        }
        __syncthreads();
        ull a01 = 0ULL, a23 = 0ULL;
        const float* hb = h_s + b * 516 + k0;
#pragma unroll 4
        for (int k = 0; k < 256; k += 4) {
            float4 hv = *(const float4*)(hb + k);
            ulonglong2 w0 = wp2[(k + 0) * 4];
            ulonglong2 w1 = wp2[(k + 1) * 4];
            ulonglong2 w2 = wp2[(k + 2) * 4];
            ulonglong2 w3 = wp2[(k + 3) * 4];
            ull h0 = packdup(hv.x), h1 = packdup(hv.y);
            ull h2 = packdup(hv.z), h3 = packdup(hv.w);
            a01 = fma2(h0, w0.x, a01); a23 = fma2(h0, w0.y, a23);
            a01 = fma2(h1, w1.x, a01); a23 = fma2(h1, w1.y, a23);
            a01 = fma2(h2, w2.x, a01); a23 = fma2(h2, w2.y, a23);
            a01 = fma2(h3, w3.x, a01); a23 = fma2(h3, w3.y, a23);
        }
        if (half) { red[ci * 2] = a01; red[ci * 2 + 1] = a23; }
        __syncthreads();
        if (!half) {
            float2 r01 = unpack2(red[ci * 2]), r23 = unpack2(red[ci * 2 + 1]);
            float2 m01 = unpack2(a01),         m23 = unpack2(a23);
            float gi = m01.x + r01.x + pg0;
            float gf = m01.y + r01.y + pg1;
            float gg = m23.x + r23.x + pg2;
            float go = m23.y + r23.y + pg3;
            c = sigf(gf) * c + sigf(gi) * tanhf(gg);
            float h = sigf(go) * tanhf(c);
            g_hidden[((size_t)(t + 1) * BATCH + b) * DIM + d] = h;
        }
        __syncthreads();
        if (tid == 0) st_rel(&g_arrive[bd], (unsigned)(t + 1));
        if (bd == 0) {
            if (tid < 128) while (ld_acq(&g_arrive[tid]) < (unsigned)(t + 1)) {}
            __syncthreads();
            if (tid == 0) st_rel(&g_go, (unsigned)(t + 1));
        } else {
            if (tid == 0) while (ld_acq(&g_go) < (unsigned)(t + 1)) {}
            __syncthreads();
        }
    }
}

// ---------------- tape loop: 1 CTA/batch, 512 threads ----------------
__global__ void __launch_bounds__(512, 1) tape_kernel(float* __restrict__ out_tape) {
    extern __shared__ float ts[];
    float* s_tape = ts;
    float* s_key  = ts + 8224;
    float* s_ro   = ts + 16448;
    float* s_act  = ts + 16704;
    ull*   s_pa   = (ull*)(ts + 17000);   // [seg*148 + j]
    float* s_pov  = ts + 17592;
    float* s_pok  = ts + 18104;
    float* s_pror = ts + 18616;
    float* s_rpos = ts + 19128;
    float* s_wpos = ts + 19256;
    float* s_rd   = ts + 19384;
    float* s_wd   = ts + 19400;
    float* s_rw   = ts + 19416;

    int b   = blockIdx.x;
    int tid = threadIdx.x;
    int m   = tid & 255;
    int seg = tid >> 8;
    int tp  = m >> 6;
    int l0  = seg << 4;

    for (int i = tid; i < 16448; i += 512) ts[i] = 0.f;
    if (tid < 256) s_ro[tid] = 0.f;
    if (tid < 128) {
        int tpp = tid >> 5, l = tid & 31;
        float v = (l == 0) ? 1.f : 0.f;
        s_rpos[tpp * 32 + l] = v;
        s_wpos[tpp * 32 + l] = v;
    }
    __syncthreads();

    for (int t = 0; t < SEQ; ++t) {
        // ---- (a) act partials: thread (seg, j); r2 range split by seg ----
        if (m < AQ2) {
            int j = m;
            ull acc0, acc1 = 0ULL;
            if (seg == 0)
                acc0 = *(const ull*)(g_actq + ((size_t)t * BATCH + b) * AQ + 2 * j);
            else
                acc0 = 0ULL;
            int rb2 = seg << 6;               // 64 r-pairs per seg
            const ulonglong2* wp = ((const ulonglong2*)g_WroP) + (size_t)rb2 * AQ2 + j;
            const float* rop = s_ro + (seg << 7);
#pragma unroll 8
            for (int r2 = 0; r2 < 64; ++r2) {
                ulonglong2 w = wp[(size_t)r2 * AQ2];
                acc0 = fma2(packdup(rop[2 * r2]),     w.x, acc0);
                acc1 = fma2(packdup(rop[2 * r2 + 1]), w.y, acc1);
            }
            s_pa[seg * AQ2 + j] = add2(acc0, acc1);
        }
        __syncthreads();
        if (tid < AQ2) {
            float2 v = unpack2(add2(s_pa[tid], s_pa[AQ2 + tid]));
            s_act[2 * tid]     = v.x;
            s_act[2 * tid + 1] = v.y;
        }
        __syncthreads();
        // ---- (b) softmaxes + gates per tape ----
        if (tid < 4) {
            const float* ab = s_act + tid * 10;
            float m0 = fmaxf(fmaxf(ab[0], ab[1]), fmaxf(ab[2], ab[3]));
            float e0 = expf(ab[0] - m0), e1 = expf(ab[1] - m0);
            float e2 = expf(ab[2] - m0), e3 = expf(ab[3] - m0);
            float inv = 1.f / (e0 + e1 + e2 + e3);
            s_rd[tid * 4 + 0] = e0 * inv; s_rd[tid * 4 + 1] = e1 * inv;
            s_rd[tid * 4 + 2] = e2 * inv; s_rd[tid * 4 + 3] = e3 * inv;
            float n0 = fmaxf(fmaxf(ab[4], ab[5]), fmaxf(ab[6], ab[7]));
            float f0 = expf(ab[4] - n0), f1 = expf(ab[5] - n0);
            float f2 = expf(ab[6] - n0), f3 = expf(ab[7] - n0);
            float jnv = 1.f / (f0 + f1 + f2 + f3);
            s_wd[tid * 4 + 0] = f0 * jnv; s_wd[tid * 4 + 1] = f1 * jnv;
            s_wd[tid * 4 + 2] = f2 * jnv; s_wd[tid * 4 + 3] = f3 * jnv;
            s_rw[tid * 2 + 0] = sigf(ab[8]);
            s_rw[tid * 2 + 1] = sigf(ab[9]);
        }
        __syncthreads();
        // ---- (c) tape/key update, l-range split across 2 segments ----
        {
            const float* frow = g_front + ((size_t)t * BATCH + b) * NFRONT;
            float v  = frow[2048 + m];
            float kk = frow[2304 + m];
            float ovp = 0.f, okp = 0.f;
#pragma unroll
            for (int l = l0; l < l0 + 16; ++l) {
                float w = s_wpos[tp * 32 + l];
                ovp = fmaf(s_tape[l * 257 + m], w, ovp);
                okp = fmaf(s_key [l * 257 + m], w, okp);
            }
            s_pov[seg * 256 + m] = ovp;
            s_pok[seg * 256 + m] = okp;
            __syncthreads();
            float rw1 = s_rw[tp * 2 + 1];
            float dv = (v  - (s_pov[m] + s_pov[256 + m])) * rw1;
            float dk = (kk - (s_pok[m] + s_pok[256 + m])) * rw1;
            float rorp = 0.f;
#pragma unroll
            for (int l = l0; l < l0 + 16; ++l) {
                float w = s_wpos[tp * 32 + l];
                float tv = s_tape[l * 257 + m] + w * dv;
                s_tape[l * 257 + m] = tv;
                rorp = fmaf(tv, s_rpos[tp * 32 + l], rorp);
                s_key[l * 257 + m] = s_key[l * 257 + m] + w * dk;
            }
            s_pror[seg * 256 + m] = rorp;
        }
        __syncthreads();
        if (tid < 256) {
            float rog = (s_pror[m] + s_pror[256 + m]) * s_rw[tp * 2 + 0];
            s_ro[m] = rog;
            g_ro[((size_t)t * BATCH + b) * MDIM + m] = rog;
        }
        // ---- (d) jpos + position updates ----
        if (tid < 128) {
            int tpp = tid >> 5, l = tid & 31;
            const float* qp = s_act + 40 + tpp * 64;
            const float* kp = s_key + l * 257 + tpp * 64;
            float aa = 0.f, ab2 = 0.f;
#pragma unroll 8
            for (int cc = 0; cc < 64; cc += 2) {
                aa  = fmaf(kp[cc],     qp[cc],     aa);
                ab2 = fmaf(kp[cc + 1], qp[cc + 1], ab2);
            }
            float acc = aa + ab2;
            float ss = acc * acc;
#pragma unroll
            for (int o = 16; o > 0; o >>= 1) ss += __shfl_xor_sync(0xffffffffu, ss, o);
            float jp = acc / fmaxf(sqrtf(ss), 1e-12f);
            float rp   = s_rpos[tpp * 32 + l];
            float rprv = s_rpos[tpp * 32 + ((l + 1) & 31)];
            float rnxt = s_rpos[tpp * 32 + ((l + 31) & 31)];
            float wp   = s_wpos[tpp * 32 + l];
            float nwp = rprv * s_wd[tpp * 4 + 0] + wp * s_wd[tpp * 4 + 1]
                      + rnxt * s_wd[tpp * 4 + 2] + jp * s_wd[tpp * 4 + 3];
            float nrp = rprv * s_rd[tpp * 4 + 0] + rp * s_rd[tpp * 4 + 1]
                      + rnxt * s_rd[tpp * 4 + 2] + jp * s_rd[tpp * 4 + 3];
            __syncwarp();
            s_wpos[tpp * 32 + l] = nwp;
            s_rpos[tpp * 32 + l] = nrp;
        }
        __syncthreads();
    }
    for (int i = tid; i < 32 * MDIM; i += 512) {
        int l = i >> 8, mm = i & 255;
        out_tape[(size_t)l * (BATCH * MDIM) + (size_t)b * MDIM + mm] = s_tape[l * 257 + mm];
    }
}

// ------------------------------- launch -------------------------------
extern "C" void kernel_launch(void* const* d_in, const int* in_sizes, int n_in,
                              void* d_out, int out_size) {
    const float* inputs = (const float*)d_in[0];
    const float* Wih    = (const float*)d_in[1];
    const float* Whh    = (const float*)d_in[2];
    const float* bih    = (const float*)d_in[3];
    const float* bhh    = (const float*)d_in[4];
    const float* Wa     = (const float*)d_in[5];
    const float* ba     = (const float*)d_in[6];
    const float* Wv     = (const float*)d_in[7];
    const float* bv     = (const float*)d_in[8];
    const float* Wk     = (const float*)d_in[9];
    const float* bk     = (const float*)d_in[10];
    const float* Wq     = (const float*)d_in[11];
    const float* bq     = (const float*)d_in[12];
    const float* Wo     = (const float*)d_in[13];
    const float* bo     = (const float*)d_in[14];
    float* out = (float*)d_out;

    float *p_front, *p_hidden, *p_actq, *p_ro, *p_Wfront, *p_bfront, *p_Wcat, *p_bcat;
    cudaGetSymbolAddress((void**)&p_front,  g_front);
    cudaGetSymbolAddress((void**)&p_hidden, g_hidden);
    cudaGetSymbolAddress((void**)&p_actq,   g_actq);
    cudaGetSymbolAddress((void**)&p_ro,     g_ro);
    cudaGetSymbolAddress((void**)&p_Wfront, g_Wfront);
    cudaGetSymbolAddress((void**)&p_bfront, g_bfront);
    cudaGetSymbolAddress((void**)&p_Wcat,   g_Wcat);
    cudaGetSymbolAddress((void**)&p_bcat,   g_bcat);

    const int LSTM_SMEM = (16512 + 8192 + 512) * 4;   // 100,864 B
    const int TAPE_SMEM = 19424 * 4;                  // 77,696 B
    cudaFuncSetAttribute(lstm_kernel, cudaFuncAttributeMaxDynamicSharedMemorySize, LSTM_SMEM);
    cudaFuncSetAttribute(tape_kernel, cudaFuncAttributeMaxDynamicSharedMemorySize, TAPE_SMEM);

    init_kernel<<<5120, 256>>>(Whh, bih, bhh, Wa, ba, Wq, bq, Wih, Wv, bv, Wk, bk);
    // fused [gates | values | keys] GEMM
    sgemm_bias<<<dim3(64, 20), 256>>>(inputs, p_Wfront, p_bfront, p_front,
                                      ROWS, NFRONT, DIM);
    knorm_kernel<<<4096, 256>>>();
    lstm_kernel<<<128, 256, LSTM_SMEM>>>();
    sgemm_bias<<<dim3(64, 3), 256>>>(p_hidden + (size_t)BATCH * DIM, p_Wcat, p_bcat,
                                     p_actq, ROWS, AQ, DIM);
    tape_kernel<<<32, 512, TAPE_SMEM>>>(out + (size_t)ROWS * DIM);
    sgemm_bias<<<dim3(64, 4), 256>>>(p_ro, Wo, bo, out, ROWS, DIM, MDIM);
}